// round 13
// baseline (speedup 1.0000x reference)
#include <cuda_runtime.h>
#include <cstdint>

// Problem constants
#define Bsz 8192
#define Dd  768
#define Wd  8192
#define Kp  32
#define TAU 1e-3f
#define MAXCAND 16

// Device scratch (allocation-free rule: __device__ globals)
__device__ float g_Adn [(size_t)Dd * Wd];   // [D, W] normalized dictionary (bit-exact vs ref)
__device__ float g_AdnT[(size_t)Wd * Dd];   // [W, D] transpose (same bits)
__device__ float g_nrm [Wd];                // clipped column norms (fp32, ref order)
__device__ float g_G   [(size_t)Wd * Wd];   // Gram matrix [W, W] (screen accuracy)
__device__ float g_Z   [(size_t)Bsz * Wd];  // initial projections (screen accuracy)

// ---------------------------------------------------------------------------
// 1) Column norms emulating the XLA:GPU column-reduction kernel:
//    per column w, 32 partials p_t = sequential mul-then-add over rows
//    d = t, t+32, t+64, ... (ascending), then the warp shfl.down butterfly
//    tree (offsets 16,8,4,2,1): a[t] += a[t+off]. Result at t=0.
//    Block = 32x32: tx = column in tile (coalesced loads), ty = partial idx.
// ---------------------------------------------------------------------------
__global__ void colnorm_kernel(const float* __restrict__ Ad) {
    __shared__ float part[32][33];
    int tx = threadIdx.x;
    int ty = threadIdx.y;
    int w = blockIdx.x * 32 + tx;

    float s = 0.f;
    #pragma unroll
    for (int i = 0; i < Dd / 32; i++) {
        float v = Ad[(size_t)(ty + 32 * i) * Wd + w];
        s = __fadd_rn(s, __fmul_rn(v, v));
    }
    part[ty][tx] = s;
    __syncthreads();

    if (ty == 0) {
        float a[32];
        #pragma unroll
        for (int t = 0; t < 32; t++) a[t] = part[t][tx];
        #pragma unroll
        for (int off = 16; off > 0; off >>= 1)
            #pragma unroll
            for (int t2 = 0; t2 < 16; t2++)
                if (t2 < off)
                    a[t2] = __fadd_rn(a[t2], a[t2 + off]);
        g_nrm[w] = fmaxf(__fsqrt_rn(a[0]), 1e-8f);
    }
}

// ---------------------------------------------------------------------------
// 2) Normalize with IEEE fp32 division (matching jnp's Ad / norm) + transpose.
// ---------------------------------------------------------------------------
__global__ void scale_kernel(const float* __restrict__ Ad) {
    size_t i = (size_t)blockIdx.x * blockDim.x + threadIdx.x;
    if (i >= (size_t)Dd * Wd) return;
    int d = (int)(i / Wd);
    int w = (int)(i % Wd);
    float v = __fdiv_rn(Ad[i], g_nrm[w]);
    g_Adn[i] = v;
    g_AdnT[(size_t)w * Dd + d] = v;
}

// ---------------------------------------------------------------------------
// 3) Fast SIMT fp32 GEMM (screen-accuracy only): C[M,N] = A[M,K] @ B[K,N]
//    MODE 1: A element = A - bias[k].  MODE 2: symmetric output, mirror-write.
//    BM=BN=128, BK=16, 256 threads, 8x8 per-thread tile. Dims must divide.
// ---------------------------------------------------------------------------
template<int MODE>
__global__ __launch_bounds__(256)
void gemm_kernel(const float* __restrict__ A,
                 const float* __restrict__ Bm,
                 const float* __restrict__ bias,
                 float* __restrict__ C,
                 int M, int N, int Kd)
{
    constexpr int BM = 128, BN = 128, BK = 16, TM = 8, TN = 8;
    __shared__ float As[BK][BM];
    __shared__ float Bs[BK][BN];

    int bx = blockIdx.x;
    int by = blockIdx.y;
    if (MODE == 2 && by > bx) return;

    int tid = threadIdx.x;
    int tx = tid % 16, ty = tid / 16;
    int m0 = by * BM, n0 = bx * BN;

    int arow = tid >> 2;           // 0..63
    int acol = (tid & 3) * 4;      // 0,4,8,12
    int brow = tid >> 5;           // 0..7
    int bcol = (tid & 31) * 4;     // 0..124

    float accum[TM][TN] = {};

    for (int k0 = 0; k0 < Kd; k0 += BK) {
        #pragma unroll
        for (int r = 0; r < 2; r++) {
            int m = m0 + arow + r * 64;
            float4 v = *(const float4*)(A + (size_t)m * Kd + k0 + acol);
            if (MODE == 1) {
                float4 bb = *(const float4*)(bias + k0 + acol);
                v.x -= bb.x; v.y -= bb.y; v.z -= bb.z; v.w -= bb.w;
            }
            As[acol + 0][arow + r * 64] = v.x;
            As[acol + 1][arow + r * 64] = v.y;
            As[acol + 2][arow + r * 64] = v.z;
            As[acol + 3][arow + r * 64] = v.w;
        }
        #pragma unroll
        for (int r = 0; r < 2; r++) {
            int kk = brow + r * 8;
            *(float4*)(&Bs[kk][bcol]) =
                *(const float4*)(Bm + (size_t)(k0 + kk) * N + n0 + bcol);
        }
        __syncthreads();

        #pragma unroll
        for (int kk = 0; kk < BK; kk++) {
            float ra[TM], rb[TN];
            #pragma unroll
            for (int i = 0; i < TM; i++) ra[i] = As[kk][ty * TM + i];
            #pragma unroll
            for (int j = 0; j < TN; j++) rb[j] = Bs[kk][tx * TN + j];
            #pragma unroll
            for (int i = 0; i < TM; i++)
                #pragma unroll
                for (int j = 0; j < TN; j++)
                    accum[i][j] = fmaf(ra[i], rb[j], accum[i][j]);
        }
        __syncthreads();
    }

    #pragma unroll
    for (int i = 0; i < TM; i++) {
        int m = m0 + ty * TM + i;
        #pragma unroll
        for (int j = 0; j < TN; j += 4) {
            int n = n0 + tx * TN + j;
            *(float4*)(C + (size_t)m * N + n) =
                make_float4(accum[i][j], accum[i][j+1], accum[i][j+2], accum[i][j+3]);
        }
    }
    if (MODE == 2 && bx != by) {
        #pragma unroll
        for (int i = 0; i < TM; i++) {
            int m = m0 + ty * TM + i;
            #pragma unroll
            for (int j = 0; j < TN; j++) {
                int n = n0 + tx * TN + j;
                C[(size_t)n * N + m] = accum[i][j];
            }
        }
    }
}

// ---------------------------------------------------------------------------
// 4) Matching pursuit, reference-arithmetic-exact selections.
//    One CTA per batch row. Fast z (Gram recurrence) screens candidates within
//    TAU of the max; each candidate gets a bit-exact fresh fp32 dot against
//    the bit-exactly maintained residual: single ascending FMA chain (the
//    per-output reduction order of cublas SIMT SGEMM / Triton fp32 tl.dot).
//    val is that exact dot value; residual updated elementwise mul-then-sub.
// ---------------------------------------------------------------------------
__global__ __launch_bounds__(256)
void mp_kernel(const float* __restrict__ x, const float* __restrict__ bd,
               float* __restrict__ out)
{
    __shared__ float z[Wd];        // 32 KB fast projections (screen)
    __shared__ float resid[Dd];    // bit-exact residual trajectory
    __shared__ float redv[256];
    __shared__ int   selIdx[Kp];
    __shared__ float selVal[Kp];
    __shared__ int   sIdx2[Kp];
    __shared__ float sVal2[Kp];
    __shared__ int   candW[MAXCAND];
    __shared__ float candZ[MAXCAND];
    __shared__ int   candCount;

    int b = blockIdx.x;
    int t = threadIdx.x;

    // resid0 = x - bd, elementwise fp32 sub (bitwise = ref; bd is zeros anyway)
    for (int d = t; d < Dd; d += 256)
        resid[d] = __fsub_rn(x[(size_t)b * Dd + d], bd[d]);
    const float* zg = g_Z + (size_t)b * Wd;
    for (int w = t; w < Wd; w += 256) z[w] = zg[w];
    __syncthreads();

    for (int k = 0; k < Kp; ++k) {
        // --- max |z| over row (value only) ---
        float bv = -1.f;
        for (int w = t; w < Wd; w += 256) {
            float a = fabsf(z[w]);
            if (a > bv) bv = a;
        }
        redv[t] = bv;
        __syncthreads();
        #pragma unroll
        for (int s = 128; s > 0; s >>= 1) {
            if (t < s) redv[t] = fmaxf(redv[t], redv[t + s]);
            __syncthreads();
        }
        float M = redv[0];
        if (t == 0) candCount = 0;
        __syncthreads();

        // --- collect candidates within TAU of max (selected entries are 0) ---
        float thr = M - TAU;
        for (int w = t; w < Wd; w += 256) {
            if (fabsf(z[w]) >= thr) {
                int pos = atomicAdd(&candCount, 1);
                if (pos < MAXCAND) candW[pos] = w;
            }
        }
        __syncthreads();
        int n = candCount < MAXCAND ? candCount : MAXCAND;

        // sort candidate indices ascending (n is tiny)
        if (t == 0) {
            for (int i = 1; i < n; i++) {
                int key = candW[i]; int j = i - 1;
                while (j >= 0 && candW[j] > key) { candW[j+1] = candW[j]; j--; }
                candW[j+1] = key;
            }
        }
        __syncthreads();

        // --- reference-order dots: single ascending fp32 FMA chain ---
        if (t < n) {
            const float* arow = g_AdnT + (size_t)candW[t] * Dd;
            float acc = 0.f;
            #pragma unroll 8
            for (int d = 0; d < Dd; d++)
                acc = __fmaf_rn(resid[d], arow[d], acc);
            candZ[t] = acc;
        }
        __syncthreads();

        // --- pick first (lowest-w) strict max of |exact z| among candidates ---
        if (t == 0) {
            int best = 0;
            for (int i = 1; i < n; i++)
                if (fabsf(candZ[i]) > fabsf(candZ[best])) best = i;
            selIdx[k] = candW[best];
            selVal[k] = candZ[best];
        }
        __syncthreads();
        int   idx = selIdx[k];
        float val = selVal[k];

        if (k < Kp - 1) {
            // bit-exact residual update: r = fsub(r, fmul(val, a))  (= ref)
            const float* arow = g_AdnT + (size_t)idx * Dd;
            for (int d = t; d < Dd; d += 256)
                resid[d] = __fsub_rn(resid[d], __fmul_rn(val, arow[d]));

            // fast z <- z - val * G[idx, :]  (screen accuracy)
            const float* grow = g_G + (size_t)idx * Wd;
            for (int w = t; w < Wd; w += 256)
                z[w] = fmaf(-val, grow[w], z[w]);
            __syncthreads();
            // force all selected entries to exactly 0 (ref's mask)
            if (t <= k) z[selIdx[t]] = 0.f;
        }
        __syncthreads();
    }

    // --- reconstruction: codes @ Adn^T as ascending-idx FMA chain + bd ---
    // (output ordering only needs 1e-3 tolerance; 1e-7 deviations are fine)
    if (t == 0) {
        for (int i = 0; i < Kp; i++) { sIdx2[i] = selIdx[i]; sVal2[i] = selVal[i]; }
        for (int i = 1; i < Kp; i++) {
            int ki = sIdx2[i]; float kv = sVal2[i]; int j = i - 1;
            while (j >= 0 && sIdx2[j] > ki) {
                sIdx2[j+1] = sIdx2[j]; sVal2[j+1] = sVal2[j]; j--;
            }
            sIdx2[j+1] = ki; sVal2[j+1] = kv;
        }
    }
    __syncthreads();

    #pragma unroll
    for (int j = 0; j < 3; j++) {
        int d = t + j * 256;
        float acc = 0.f;
        #pragma unroll 1
        for (int i = 0; i < Kp; i++)
            acc = __fmaf_rn(sVal2[i], g_AdnT[(size_t)sIdx2[i] * Dd + d], acc);
        out[(size_t)b * Dd + d] = __fadd_rn(acc, bd[d]);
    }
}

// ---------------------------------------------------------------------------
// Launch
// ---------------------------------------------------------------------------
extern "C" void kernel_launch(void* const* d_in, const int* in_sizes, int n_in,
                              void* d_out, int out_size)
{
    const float* x  = (const float*)d_in[0];   // [B, D]
    const float* Ad = (const float*)d_in[1];   // [D, W]
    const float* bd = (const float*)d_in[2];   // [1, D]
    float* out = (float*)d_out;                // [B, D]

    float *p_Adn, *p_AdnT, *p_G, *p_Z;
    cudaGetSymbolAddress((void**)&p_Adn,  g_Adn);
    cudaGetSymbolAddress((void**)&p_AdnT, g_AdnT);
    cudaGetSymbolAddress((void**)&p_G,    g_G);
    cudaGetSymbolAddress((void**)&p_Z,    g_Z);

    // 1) column norms (XLA:GPU column-reduce order: 32 stride-32 partials +
    //    shfl.down butterfly tree)
    colnorm_kernel<<<Wd / 32, dim3(32, 32)>>>(Ad);

    // 2) normalize + transpose (IEEE fp32 division)
    {
        size_t total = (size_t)Dd * Wd;
        int threads = 256;
        int blocks = (int)((total + threads - 1) / threads);
        scale_kernel<<<blocks, threads>>>(Ad);
    }

    // 3) G = AdnT @ Adn   (symmetric, screen accuracy)
    gemm_kernel<2><<<dim3(Wd / 128, Wd / 128), 256>>>(p_AdnT, p_Adn, nullptr,
                                                      p_G, Wd, Wd, Dd);

    // 4) z0 = (x - bd) @ Adn  (screen accuracy)
    gemm_kernel<1><<<dim3(Wd / 128, Bsz / 128), 256>>>(x, p_Adn, bd,
                                                       p_Z, Bsz, Wd, Dd);

    // 5) matching pursuit with reference-exact selection + reconstruction
    mp_kernel<<<Bsz, 256>>>(x, bd, out);
}

// round 14
// speedup vs baseline: 1.2025x; 1.2025x over previous
#include <cuda_runtime.h>
#include <cstdint>

// Problem constants
#define Bsz 8192
#define Dd  768
#define Wd  8192
#define Kp  32
#define TAU 5e-3f
#define MAXCAND 24

// Device scratch (allocation-free rule: __device__ globals)
__device__ float g_Adn [(size_t)Dd * Wd];   // [D, W] normalized dictionary (bit-exact vs ref)
__device__ float g_AdnT[(size_t)Wd * Dd];   // [W, D] transpose (same bits)
__device__ float g_nrm [Wd];                // clipped column norms (fp32, ref order)
__device__ float g_G   [(size_t)Wd * Wd];   // Gram matrix [W, W] (screen accuracy, tf32)
__device__ float g_Z   [(size_t)Bsz * Wd];  // initial projections (screen accuracy, tf32)

// ---------------------------------------------------------------------------
// 1) Column norms emulating the XLA:GPU column-reduction kernel (BIT-CRITICAL):
//    per column w, 32 partials p_t = sequential mul-then-add over rows
//    d = t, t+32, ... (ascending), then shfl.down butterfly (16,8,4,2,1).
// ---------------------------------------------------------------------------
__global__ void colnorm_kernel(const float* __restrict__ Ad) {
    __shared__ float part[32][33];
    int tx = threadIdx.x;
    int ty = threadIdx.y;
    int w = blockIdx.x * 32 + tx;

    float s = 0.f;
    #pragma unroll
    for (int i = 0; i < Dd / 32; i++) {
        float v = Ad[(size_t)(ty + 32 * i) * Wd + w];
        s = __fadd_rn(s, __fmul_rn(v, v));
    }
    part[ty][tx] = s;
    __syncthreads();

    if (ty == 0) {
        float a[32];
        #pragma unroll
        for (int t = 0; t < 32; t++) a[t] = part[t][tx];
        #pragma unroll
        for (int off = 16; off > 0; off >>= 1)
            #pragma unroll
            for (int t2 = 0; t2 < 16; t2++)
                if (t2 < off)
                    a[t2] = __fadd_rn(a[t2], a[t2 + off]);
        g_nrm[w] = fmaxf(__fsqrt_rn(a[0]), 1e-8f);
    }
}

// ---------------------------------------------------------------------------
// 2) Normalize with IEEE fp32 division (BIT-CRITICAL) + transpose.
// ---------------------------------------------------------------------------
__global__ void scale_kernel(const float* __restrict__ Ad) {
    size_t i = (size_t)blockIdx.x * blockDim.x + threadIdx.x;
    if (i >= (size_t)Dd * Wd) return;
    int d = (int)(i / Wd);
    int w = (int)(i % Wd);
    float v = __fdiv_rn(Ad[i], g_nrm[w]);
    g_Adn[i] = v;
    g_AdnT[(size_t)w * Dd + d] = v;
}

// ---------------------------------------------------------------------------
// 3) tf32 tensor-core GEMM (screen accuracy): C[M,N] = A[M,K] @ B[K,N]
//    MODE 0: plain.  MODE 1: A element = A - bias[k].
//    BM=BN=128, BK=32. 256 threads = 8 warps in 2(m) x 4(n); warp tile 64x32
//    via mma.sync.m16n8k8 (4 m-frags x 4 n-frags x 4 k-steps).
//    Inputs cvt.rna to tf32 on the smem-store path; fp32 accumulate.
// ---------------------------------------------------------------------------
__device__ __forceinline__ float tf32r(float x) {
    uint32_t r;
    asm("cvt.rna.tf32.f32 %0, %1;" : "=r"(r) : "f"(x));
    return __uint_as_float(r);
}

__device__ __forceinline__ void mma_tf32(
    float& d0, float& d1, float& d2, float& d3,
    float a0, float a1, float a2, float a3,
    float b0, float b1)
{
    asm volatile(
        "mma.sync.aligned.m16n8k8.row.col.f32.tf32.tf32.f32 "
        "{%0,%1,%2,%3}, {%4,%5,%6,%7}, {%8,%9}, {%0,%1,%2,%3};\n"
        : "+f"(d0), "+f"(d1), "+f"(d2), "+f"(d3)
        : "r"(__float_as_uint(a0)), "r"(__float_as_uint(a1)),
          "r"(__float_as_uint(a2)), "r"(__float_as_uint(a3)),
          "r"(__float_as_uint(b0)), "r"(__float_as_uint(b1)));
}

template<int MODE>
__global__ __launch_bounds__(256)
void gemm_tf32_kernel(const float* __restrict__ A,
                      const float* __restrict__ Bm,
                      const float* __restrict__ bias,
                      float* __restrict__ C,
                      int M, int N, int Kd)
{
    constexpr int BM = 128, BN = 128, BK = 32;
    constexpr int ASTR = BK + 4;    // 36 floats: conflict-free frag loads
    constexpr int BSTR = BN + 8;    // 136 floats: bank = 8k+n, unique
    __shared__ float As[BM * ASTR];
    __shared__ float Bs[BK * BSTR];

    int tid  = threadIdx.x;
    int lane = tid & 31;
    int warp = tid >> 5;
    int wm = warp >> 2;             // 0..1
    int wn = warp & 3;              // 0..3

    int m0 = blockIdx.y * BM;
    int n0 = blockIdx.x * BN;

    float acc[4][4][4] = {};        // [mi][ni][dreg]

    for (int k0 = 0; k0 < Kd; k0 += BK) {
        // --- load A tile (BM x BK), cvt to tf32, float4 smem stores ---
        {
            int r0 = tid >> 3;              // 0..31
            int c  = (tid & 7) * 4;         // 0..28
            #pragma unroll
            for (int p = 0; p < 4; p++) {
                int r = r0 + p * 32;
                float4 v = *(const float4*)(A + (size_t)(m0 + r) * Kd + k0 + c);
                if (MODE == 1) {
                    float4 bb = *(const float4*)(bias + k0 + c);
                    v.x -= bb.x; v.y -= bb.y; v.z -= bb.z; v.w -= bb.w;
                }
                v.x = tf32r(v.x); v.y = tf32r(v.y);
                v.z = tf32r(v.z); v.w = tf32r(v.w);
                *(float4*)(&As[r * ASTR + c]) = v;
            }
        }
        // --- load B tile (BK x BN), cvt to tf32 ---
        {
            int kr0 = tid >> 5;             // 0..7
            int nc  = (tid & 31) * 4;       // 0..124
            #pragma unroll
            for (int p = 0; p < 4; p++) {
                int kr = kr0 + p * 8;
                float4 v = *(const float4*)(Bm + (size_t)(k0 + kr) * N + n0 + nc);
                v.x = tf32r(v.x); v.y = tf32r(v.y);
                v.z = tf32r(v.z); v.w = tf32r(v.w);
                *(float4*)(&Bs[kr * BSTR + nc]) = v;
            }
        }
        __syncthreads();

        #pragma unroll
        for (int ks = 0; ks < BK / 8; ks++) {
            int kc = ks * 8;
            float af[4][4];
            #pragma unroll
            for (int mi = 0; mi < 4; mi++) {
                int rb = wm * 64 + mi * 16;
                int r0 = rb + (lane >> 2);
                int c0 = kc + (lane & 3);
                af[mi][0] = As[r0 * ASTR + c0];
                af[mi][1] = As[(r0 + 8) * ASTR + c0];
                af[mi][2] = As[r0 * ASTR + c0 + 4];
                af[mi][3] = As[(r0 + 8) * ASTR + c0 + 4];
            }
            float bf[4][2];
            #pragma unroll
            for (int ni = 0; ni < 4; ni++) {
                int nb = wn * 32 + ni * 8 + (lane >> 2);
                int kb = kc + (lane & 3);
                bf[ni][0] = Bs[kb * BSTR + nb];
                bf[ni][1] = Bs[(kb + 4) * BSTR + nb];
            }
            #pragma unroll
            for (int mi = 0; mi < 4; mi++)
                #pragma unroll
                for (int ni = 0; ni < 4; ni++)
                    mma_tf32(acc[mi][ni][0], acc[mi][ni][1],
                             acc[mi][ni][2], acc[mi][ni][3],
                             af[mi][0], af[mi][1], af[mi][2], af[mi][3],
                             bf[ni][0], bf[ni][1]);
        }
        __syncthreads();
    }

    // --- epilogue: scatter accumulators ---
    #pragma unroll
    for (int mi = 0; mi < 4; mi++) {
        int rb = m0 + wm * 64 + mi * 16 + (lane >> 2);
        #pragma unroll
        for (int ni = 0; ni < 4; ni++) {
            int cb = n0 + wn * 32 + ni * 8 + 2 * (lane & 3);
            C[(size_t)rb * N + cb]           = acc[mi][ni][0];
            C[(size_t)rb * N + cb + 1]       = acc[mi][ni][1];
            C[(size_t)(rb + 8) * N + cb]     = acc[mi][ni][2];
            C[(size_t)(rb + 8) * N + cb + 1] = acc[mi][ni][3];
        }
    }
}

// ---------------------------------------------------------------------------
// 4) Matching pursuit, reference-arithmetic-exact selections (BIT-CRITICAL
//    parts unchanged from the passing round): screen z now has tf32-level
//    error, covered by TAU=5e-3; selection decided by bit-exact fp32 dots.
// ---------------------------------------------------------------------------
__global__ __launch_bounds__(256)
void mp_kernel(const float* __restrict__ x, const float* __restrict__ bd,
               float* __restrict__ out)
{
    __shared__ float z[Wd];        // 32 KB fast projections (screen)
    __shared__ float resid[Dd];    // bit-exact residual trajectory
    __shared__ float redv[256];
    __shared__ int   selIdx[Kp];
    __shared__ float selVal[Kp];
    __shared__ int   sIdx2[Kp];
    __shared__ float sVal2[Kp];
    __shared__ int   candW[MAXCAND];
    __shared__ float candZ[MAXCAND];
    __shared__ int   candCount;

    int b = blockIdx.x;
    int t = threadIdx.x;

    // resid0 = x - bd, elementwise fp32 sub (bitwise = ref)
    for (int d = t; d < Dd; d += 256)
        resid[d] = __fsub_rn(x[(size_t)b * Dd + d], bd[d]);
    const float* zg = g_Z + (size_t)b * Wd;
    for (int w = t; w < Wd; w += 256) z[w] = zg[w];
    __syncthreads();

    for (int k = 0; k < Kp; ++k) {
        // --- max |z| over row (screen values) ---
        float bv = -1.f;
        for (int w = t; w < Wd; w += 256) {
            float a = fabsf(z[w]);
            if (a > bv) bv = a;
        }
        redv[t] = bv;
        __syncthreads();
        #pragma unroll
        for (int s = 128; s > 0; s >>= 1) {
            if (t < s) redv[t] = fmaxf(redv[t], redv[t + s]);
            __syncthreads();
        }
        float M = redv[0];
        if (t == 0) candCount = 0;
        __syncthreads();

        // --- collect candidates within TAU of max (selected entries are 0) ---
        float thr = M - TAU;
        for (int w = t; w < Wd; w += 256) {
            if (fabsf(z[w]) >= thr) {
                int pos = atomicAdd(&candCount, 1);
                if (pos < MAXCAND) candW[pos] = w;
            }
        }
        __syncthreads();
        int n = candCount < MAXCAND ? candCount : MAXCAND;

        // sort candidate indices ascending (n is tiny)
        if (t == 0) {
            for (int i = 1; i < n; i++) {
                int key = candW[i]; int j = i - 1;
                while (j >= 0 && candW[j] > key) { candW[j+1] = candW[j]; j--; }
                candW[j+1] = key;
            }
        }
        __syncthreads();

        // --- BIT-CRITICAL: single ascending fp32 FMA chain dots ---
        if (t < n) {
            const float* arow = g_AdnT + (size_t)candW[t] * Dd;
            float acc = 0.f;
            #pragma unroll 8
            for (int d = 0; d < Dd; d++)
                acc = __fmaf_rn(resid[d], arow[d], acc);
            candZ[t] = acc;
        }
        __syncthreads();

        // --- pick first (lowest-w) strict max of |exact z| among candidates ---
        if (t == 0) {
            int best = 0;
            for (int i = 1; i < n; i++)
                if (fabsf(candZ[i]) > fabsf(candZ[best])) best = i;
            selIdx[k] = candW[best];
            selVal[k] = candZ[best];
        }
        __syncthreads();
        int   idx = selIdx[k];
        float val = selVal[k];

        if (k < Kp - 1) {
            // BIT-CRITICAL residual update: r = fsub(r, fmul(val, a))
            const float* arow = g_AdnT + (size_t)idx * Dd;
            for (int d = t; d < Dd; d += 256)
                resid[d] = __fsub_rn(resid[d], __fmul_rn(val, arow[d]));

            // fast z <- z - val * G[idx, :]  (screen accuracy)
            const float* grow = g_G + (size_t)idx * Wd;
            for (int w = t; w < Wd; w += 256)
                z[w] = fmaf(-val, grow[w], z[w]);
            __syncthreads();
            // force all selected entries to exactly 0 (ref's mask)
            if (t <= k) z[selIdx[t]] = 0.f;
        }
        __syncthreads();
    }

    // --- reconstruction: codes @ Adn^T as ascending-idx FMA chain + bd ---
    if (t == 0) {
        for (int i = 0; i < Kp; i++) { sIdx2[i] = selIdx[i]; sVal2[i] = selVal[i]; }
        for (int i = 1; i < Kp; i++) {
            int ki = sIdx2[i]; float kv = sVal2[i]; int j = i - 1;
            while (j >= 0 && sIdx2[j] > ki) {
                sIdx2[j+1] = sIdx2[j]; sVal2[j+1] = sVal2[j]; j--;
            }
            sIdx2[j+1] = ki; sVal2[j+1] = kv;
        }
    }
    __syncthreads();

    #pragma unroll
    for (int j = 0; j < 3; j++) {
        int d = t + j * 256;
        float acc = 0.f;
        #pragma unroll 1
        for (int i = 0; i < Kp; i++)
            acc = __fmaf_rn(sVal2[i], g_AdnT[(size_t)sIdx2[i] * Dd + d], acc);
        out[(size_t)b * Dd + d] = __fadd_rn(acc, bd[d]);
    }
}

// ---------------------------------------------------------------------------
// Launch
// ---------------------------------------------------------------------------
extern "C" void kernel_launch(void* const* d_in, const int* in_sizes, int n_in,
                              void* d_out, int out_size)
{
    const float* x  = (const float*)d_in[0];   // [B, D]
    const float* Ad = (const float*)d_in[1];   // [D, W]
    const float* bd = (const float*)d_in[2];   // [1, D]
    float* out = (float*)d_out;                // [B, D]

    float *p_Adn, *p_AdnT, *p_G, *p_Z;
    cudaGetSymbolAddress((void**)&p_Adn,  g_Adn);
    cudaGetSymbolAddress((void**)&p_AdnT, g_AdnT);
    cudaGetSymbolAddress((void**)&p_G,    g_G);
    cudaGetSymbolAddress((void**)&p_Z,    g_Z);

    // 1) column norms (XLA:GPU column-reduce order — BIT-CRITICAL)
    colnorm_kernel<<<Wd / 32, dim3(32, 32)>>>(Ad);

    // 2) normalize + transpose (BIT-CRITICAL)
    {
        size_t total = (size_t)Dd * Wd;
        int threads = 256;
        int blocks = (int)((total + threads - 1) / threads);
        scale_kernel<<<blocks, threads>>>(Ad);
    }

    // 3) G = AdnT @ Adn   (tf32 tensor cores, screen accuracy)
    gemm_tf32_kernel<0><<<dim3(Wd / 128, Wd / 128), 256>>>(
        p_AdnT, p_Adn, nullptr, p_G, Wd, Wd, Dd);

    // 4) z0 = (x - bd) @ Adn  (tf32 tensor cores, screen accuracy)
    gemm_tf32_kernel<1><<<dim3(Wd / 128, Bsz / 128), 256>>>(
        x, p_Adn, bd, p_Z, Bsz, Wd, Dd);

    // 5) matching pursuit with reference-exact selection + reconstruction
    mp_kernel<<<Bsz, 256>>>(x, bd, out);
}

// round 15
// speedup vs baseline: 2.3433x; 1.9487x over previous
#include <cuda_runtime.h>
#include <cstdint>

// Problem constants
#define Bsz 8192
#define Dd  768
#define Wd  8192
#define Kp  32
#define TAU 5e-3f
#define MAXCAND 24
#define CSTR 772   // staged candidate row stride (768 + 4: bank-shifted, 16B-mult)

// Device scratch (allocation-free rule: __device__ globals)
__device__ float g_Adn [(size_t)Dd * Wd];   // [D, W] normalized dictionary (bit-exact vs ref)
__device__ float g_AdnT[(size_t)Wd * Dd];   // [W, D] transpose (same bits)
__device__ float g_nrm [Wd];                // clipped column norms (fp32, ref order)
__device__ float g_G   [(size_t)Wd * Wd];   // Gram matrix [W, W] (screen accuracy, tf32)
__device__ float g_Z   [(size_t)Bsz * Wd];  // initial projections (screen accuracy, tf32)

// ---------------------------------------------------------------------------
// 1) Column norms emulating the XLA:GPU column-reduction kernel (BIT-CRITICAL):
//    per column w, 32 partials p_t = sequential mul-then-add over rows
//    d = t, t+32, ... (ascending), then shfl.down butterfly (16,8,4,2,1).
// ---------------------------------------------------------------------------
__global__ void colnorm_kernel(const float* __restrict__ Ad) {
    __shared__ float part[32][33];
    int tx = threadIdx.x;
    int ty = threadIdx.y;
    int w = blockIdx.x * 32 + tx;

    float s = 0.f;
    #pragma unroll
    for (int i = 0; i < Dd / 32; i++) {
        float v = Ad[(size_t)(ty + 32 * i) * Wd + w];
        s = __fadd_rn(s, __fmul_rn(v, v));
    }
    part[ty][tx] = s;
    __syncthreads();

    if (ty == 0) {
        float a[32];
        #pragma unroll
        for (int t = 0; t < 32; t++) a[t] = part[t][tx];
        #pragma unroll
        for (int off = 16; off > 0; off >>= 1)
            #pragma unroll
            for (int t2 = 0; t2 < 16; t2++)
                if (t2 < off)
                    a[t2] = __fadd_rn(a[t2], a[t2 + off]);
        g_nrm[w] = fmaxf(__fsqrt_rn(a[0]), 1e-8f);
    }
}

// ---------------------------------------------------------------------------
// 2) Normalize with IEEE fp32 division (BIT-CRITICAL) + transpose.
// ---------------------------------------------------------------------------
__global__ void scale_kernel(const float* __restrict__ Ad) {
    size_t i = (size_t)blockIdx.x * blockDim.x + threadIdx.x;
    if (i >= (size_t)Dd * Wd) return;
    int d = (int)(i / Wd);
    int w = (int)(i % Wd);
    float v = __fdiv_rn(Ad[i], g_nrm[w]);
    g_Adn[i] = v;
    g_AdnT[(size_t)w * Dd + d] = v;
}

// ---------------------------------------------------------------------------
// 3) tf32 tensor-core GEMM (screen accuracy): C[M,N] = A[M,K] @ B[K,N]
//    MODE 0: plain.  MODE 1: A element = A - bias[k].
// ---------------------------------------------------------------------------
__device__ __forceinline__ float tf32r(float x) {
    uint32_t r;
    asm("cvt.rna.tf32.f32 %0, %1;" : "=r"(r) : "f"(x));
    return __uint_as_float(r);
}

__device__ __forceinline__ void mma_tf32(
    float& d0, float& d1, float& d2, float& d3,
    float a0, float a1, float a2, float a3,
    float b0, float b1)
{
    asm volatile(
        "mma.sync.aligned.m16n8k8.row.col.f32.tf32.tf32.f32 "
        "{%0,%1,%2,%3}, {%4,%5,%6,%7}, {%8,%9}, {%0,%1,%2,%3};\n"
        : "+f"(d0), "+f"(d1), "+f"(d2), "+f"(d3)
        : "r"(__float_as_uint(a0)), "r"(__float_as_uint(a1)),
          "r"(__float_as_uint(a2)), "r"(__float_as_uint(a3)),
          "r"(__float_as_uint(b0)), "r"(__float_as_uint(b1)));
}

template<int MODE>
__global__ __launch_bounds__(256)
void gemm_tf32_kernel(const float* __restrict__ A,
                      const float* __restrict__ Bm,
                      const float* __restrict__ bias,
                      float* __restrict__ C,
                      int M, int N, int Kd)
{
    constexpr int BM = 128, BN = 128, BK = 32;
    constexpr int ASTR = BK + 4;
    constexpr int BSTR = BN + 8;
    __shared__ float As[BM * ASTR];
    __shared__ float Bs[BK * BSTR];

    int tid  = threadIdx.x;
    int lane = tid & 31;
    int warp = tid >> 5;
    int wm = warp >> 2;
    int wn = warp & 3;

    int m0 = blockIdx.y * BM;
    int n0 = blockIdx.x * BN;

    float acc[4][4][4] = {};

    for (int k0 = 0; k0 < Kd; k0 += BK) {
        {
            int r0 = tid >> 3;
            int c  = (tid & 7) * 4;
            #pragma unroll
            for (int p = 0; p < 4; p++) {
                int r = r0 + p * 32;
                float4 v = *(const float4*)(A + (size_t)(m0 + r) * Kd + k0 + c);
                if (MODE == 1) {
                    float4 bb = *(const float4*)(bias + k0 + c);
                    v.x -= bb.x; v.y -= bb.y; v.z -= bb.z; v.w -= bb.w;
                }
                v.x = tf32r(v.x); v.y = tf32r(v.y);
                v.z = tf32r(v.z); v.w = tf32r(v.w);
                *(float4*)(&As[r * ASTR + c]) = v;
            }
        }
        {
            int kr0 = tid >> 5;
            int nc  = (tid & 31) * 4;
            #pragma unroll
            for (int p = 0; p < 4; p++) {
                int kr = kr0 + p * 8;
                float4 v = *(const float4*)(Bm + (size_t)(k0 + kr) * N + n0 + nc);
                v.x = tf32r(v.x); v.y = tf32r(v.y);
                v.z = tf32r(v.z); v.w = tf32r(v.w);
                *(float4*)(&Bs[kr * BSTR + nc]) = v;
            }
        }
        __syncthreads();

        #pragma unroll
        for (int ks = 0; ks < BK / 8; ks++) {
            int kc = ks * 8;
            float af[4][4];
            #pragma unroll
            for (int mi = 0; mi < 4; mi++) {
                int rb = wm * 64 + mi * 16;
                int r0 = rb + (lane >> 2);
                int c0 = kc + (lane & 3);
                af[mi][0] = As[r0 * ASTR + c0];
                af[mi][1] = As[(r0 + 8) * ASTR + c0];
                af[mi][2] = As[r0 * ASTR + c0 + 4];
                af[mi][3] = As[(r0 + 8) * ASTR + c0 + 4];
            }
            float bf[4][2];
            #pragma unroll
            for (int ni = 0; ni < 4; ni++) {
                int nb = wn * 32 + ni * 8 + (lane >> 2);
                int kb = kc + (lane & 3);
                bf[ni][0] = Bs[kb * BSTR + nb];
                bf[ni][1] = Bs[(kb + 4) * BSTR + nb];
            }
            #pragma unroll
            for (int mi = 0; mi < 4; mi++)
                #pragma unroll
                for (int ni = 0; ni < 4; ni++)
                    mma_tf32(acc[mi][ni][0], acc[mi][ni][1],
                             acc[mi][ni][2], acc[mi][ni][3],
                             af[mi][0], af[mi][1], af[mi][2], af[mi][3],
                             bf[ni][0], bf[ni][1]);
        }
        __syncthreads();
    }

    #pragma unroll
    for (int mi = 0; mi < 4; mi++) {
        int rb = m0 + wm * 64 + mi * 16 + (lane >> 2);
        #pragma unroll
        for (int ni = 0; ni < 4; ni++) {
            int cb = n0 + wn * 32 + ni * 8 + 2 * (lane & 3);
            C[(size_t)rb * N + cb]           = acc[mi][ni][0];
            C[(size_t)rb * N + cb + 1]       = acc[mi][ni][1];
            C[(size_t)(rb + 8) * N + cb]     = acc[mi][ni][2];
            C[(size_t)(rb + 8) * N + cb + 1] = acc[mi][ni][3];
        }
    }
}

// ---------------------------------------------------------------------------
// 4) Matching pursuit v2. BIT-CRITICAL ops unchanged: resid init/update
//    (fsub/fmul elementwise), candidate dots as single ascending fp32 FMA
//    chains (now fed from smem-staged rows — same bits, same order), lowest-
//    index strict-max pick. Screen: float4 passes, shared atomicMax for max|z|.
// ---------------------------------------------------------------------------
__global__ __launch_bounds__(256)
void mp_kernel(const float* __restrict__ x, const float* __restrict__ bd,
               float* __restrict__ out)
{
    __shared__ __align__(16) float z[Wd];          // 32 KB screen projections
    __shared__ __align__(16) float resid[Dd];      // bit-exact residual
    __shared__ __align__(16) float cbuf[2 * CSTR]; // staged candidate rows
    __shared__ int   selIdx[Kp];
    __shared__ float selVal[Kp];
    __shared__ int   sIdx2[Kp];
    __shared__ float sVal2[Kp];
    __shared__ int   candW[MAXCAND];
    __shared__ float candZ[MAXCAND];
    __shared__ int   candCount;
    __shared__ int   sMaxBits;

    int b = blockIdx.x;
    int t = threadIdx.x;

    // resid0 = x - bd, elementwise fp32 sub (BIT-CRITICAL)
    for (int d = t; d < Dd; d += 256)
        resid[d] = __fsub_rn(x[(size_t)b * Dd + d], bd[d]);
    // load screen z (float4)
    {
        const float* zg = g_Z + (size_t)b * Wd;
        #pragma unroll
        for (int i = 0; i < 8; i++) {
            int base = i * 1024 + t * 4;
            *(float4*)(&z[base]) = *(const float4*)(zg + base);
        }
    }
    __syncthreads();

    for (int k = 0; k < Kp; ++k) {
        // --- Phase A: max |z| via shared atomicMax on float bits ---
        if (t == 0) { sMaxBits = 0; candCount = 0; }
        __syncthreads();
        {
            float bv = 0.f;
            #pragma unroll
            for (int i = 0; i < 8; i++) {
                float4 v = *(const float4*)(&z[i * 1024 + t * 4]);
                bv = fmaxf(bv, fmaxf(fmaxf(fabsf(v.x), fabsf(v.y)),
                                     fmaxf(fabsf(v.z), fabsf(v.w))));
            }
            atomicMax(&sMaxBits, __float_as_int(bv));
        }
        __syncthreads();
        float M = __int_as_float(sMaxBits);

        // --- Phase B: collect candidates within TAU of max ---
        float thr = M - TAU;
        #pragma unroll
        for (int i = 0; i < 8; i++) {
            int base = i * 1024 + t * 4;
            float4 v = *(const float4*)(&z[base]);
            #pragma unroll
            for (int j = 0; j < 4; j++) {
                float a = fabsf(((const float*)&v)[j]);
                if (a >= thr) {
                    int pos = atomicAdd(&candCount, 1);
                    if (pos < MAXCAND) candW[pos] = base + j;
                }
            }
        }
        __syncthreads();
        int n = candCount < MAXCAND ? candCount : MAXCAND;

        // sort candidate indices ascending (n is ~1)
        if (t == 0) {
            for (int i = 1; i < n; i++) {
                int key = candW[i]; int j = i - 1;
                while (j >= 0 && candW[j] > key) { candW[j+1] = candW[j]; j--; }
                candW[j+1] = key;
            }
        }
        __syncthreads();

        // --- Phase C: stage rows (coalesced) + BIT-CRITICAL serial chains ---
        for (int base = 0; base < n; base += 2) {
            int cnt = n - base; if (cnt > 2) cnt = 2;
            for (int r = 0; r < cnt; r++) {
                const float* arow = g_AdnT + (size_t)candW[base + r] * Dd;
                if (t < 192)
                    *(float4*)(&cbuf[r * CSTR + t * 4]) =
                        *(const float4*)(arow + t * 4);
            }
            __syncthreads();
            if (t < cnt) {
                const float* crow = &cbuf[t * CSTR];
                float acc = 0.f;
                #pragma unroll 16
                for (int d = 0; d < Dd; d++)
                    acc = __fmaf_rn(resid[d], crow[d], acc);
                candZ[base + t] = acc;
            }
            __syncthreads();
        }

        // --- Phase D: pick first (lowest-w) strict max of |exact z| ---
        if (t == 0) {
            int best = 0;
            for (int i = 1; i < n; i++)
                if (fabsf(candZ[i]) > fabsf(candZ[best])) best = i;
            selIdx[k] = candW[best];
            selVal[k] = candZ[best];
        }
        __syncthreads();
        int   idx = selIdx[k];
        float val = selVal[k];

        // --- Phase E: updates ---
        if (k < Kp - 1) {
            // BIT-CRITICAL residual update: r = fsub(r, fmul(val, a))
            const float* arow = g_AdnT + (size_t)idx * Dd;
            for (int d = t; d < Dd; d += 256)
                resid[d] = __fsub_rn(resid[d], __fmul_rn(val, arow[d]));

            // screen z update: z -= val * G[idx,:]  (float4, coalesced)
            const float* grow = g_G + (size_t)idx * Wd;
            #pragma unroll
            for (int i = 0; i < 8; i++) {
                int base = i * 1024 + t * 4;
                float4 g = *(const float4*)(grow + base);
                float4 zz = *(const float4*)(&z[base]);
                zz.x = fmaf(-val, g.x, zz.x);
                zz.y = fmaf(-val, g.y, zz.y);
                zz.z = fmaf(-val, g.z, zz.z);
                zz.w = fmaf(-val, g.w, zz.w);
                *(float4*)(&z[base]) = zz;
            }
            __syncthreads();
            // force all selected entries to exactly 0 (ref's mask)
            if (t <= k) z[selIdx[t]] = 0.f;
        }
        __syncthreads();
    }

    // --- reconstruction: codes @ Adn^T as ascending-idx FMA chain + bd ---
    if (t == 0) {
        for (int i = 0; i < Kp; i++) { sIdx2[i] = selIdx[i]; sVal2[i] = selVal[i]; }
        for (int i = 1; i < Kp; i++) {
            int ki = sIdx2[i]; float kv = sVal2[i]; int j = i - 1;
            while (j >= 0 && sIdx2[j] > ki) {
                sIdx2[j+1] = sIdx2[j]; sVal2[j+1] = sVal2[j]; j--;
            }
            sIdx2[j+1] = ki; sVal2[j+1] = kv;
        }
    }
    __syncthreads();

    #pragma unroll
    for (int j = 0; j < 3; j++) {
        int d = t + j * 256;
        float acc = 0.f;
        #pragma unroll 1
        for (int i = 0; i < Kp; i++)
            acc = __fmaf_rn(sVal2[i], g_AdnT[(size_t)sIdx2[i] * Dd + d], acc);
        out[(size_t)b * Dd + d] = __fadd_rn(acc, bd[d]);
    }
}

// ---------------------------------------------------------------------------
// Launch
// ---------------------------------------------------------------------------
extern "C" void kernel_launch(void* const* d_in, const int* in_sizes, int n_in,
                              void* d_out, int out_size)
{
    const float* x  = (const float*)d_in[0];   // [B, D]
    const float* Ad = (const float*)d_in[1];   // [D, W]
    const float* bd = (const float*)d_in[2];   // [1, D]
    float* out = (float*)d_out;                // [B, D]

    float *p_Adn, *p_AdnT, *p_G, *p_Z;
    cudaGetSymbolAddress((void**)&p_Adn,  g_Adn);
    cudaGetSymbolAddress((void**)&p_AdnT, g_AdnT);
    cudaGetSymbolAddress((void**)&p_G,    g_G);
    cudaGetSymbolAddress((void**)&p_Z,    g_Z);

    // 1) column norms (XLA:GPU column-reduce order — BIT-CRITICAL)
    colnorm_kernel<<<Wd / 32, dim3(32, 32)>>>(Ad);

    // 2) normalize + transpose (BIT-CRITICAL)
    {
        size_t total = (size_t)Dd * Wd;
        int threads = 256;
        int blocks = (int)((total + threads - 1) / threads);
        scale_kernel<<<blocks, threads>>>(Ad);
    }

    // 3) G = AdnT @ Adn   (tf32 tensor cores, screen accuracy)
    gemm_tf32_kernel<0><<<dim3(Wd / 128, Wd / 128), 256>>>(
        p_AdnT, p_Adn, nullptr, p_G, Wd, Wd, Dd);

    // 4) z0 = (x - bd) @ Adn  (tf32 tensor cores, screen accuracy)
    gemm_tf32_kernel<1><<<dim3(Wd / 128, Bsz / 128), 256>>>(
        x, p_Adn, bd, p_Z, Bsz, Wd, Dd);

    // 5) matching pursuit with reference-exact selection + reconstruction
    mp_kernel<<<Bsz, 256>>>(x, bd, out);
}

// round 16
// speedup vs baseline: 2.5214x; 1.0760x over previous
#include <cuda_runtime.h>
#include <cuda_fp16.h>
#include <cstdint>

// Problem constants
#define Bsz 8192
#define Dd  768
#define Wd  8192
#define Kp  32
#define TAU 5e-3f
#define MAXCAND 24
#define CSTR 772   // staged candidate row stride (768 + 4)

// Device scratch (allocation-free rule: __device__ globals)
__device__ float  g_Adn [(size_t)Dd * Wd];   // [D, W] normalized dictionary (bit-exact)
__device__ float  g_AdnT[(size_t)Wd * Dd];   // [W, D] transpose (same bits)
__device__ float  g_nrm [Wd];                // clipped column norms (ref order)
__device__ __half g_Gh  [(size_t)Wd * Wd];   // Gram matrix (fp16, screen accuracy)
__device__ float  g_Z   [(size_t)Bsz * Wd];  // initial projections (screen accuracy)
__device__ float  g_Xm  [(size_t)Bsz * Dd];  // x - bd (screen input to z0 GEMM)

// ---------------------------------------------------------------------------
// 1) Column norms emulating the XLA:GPU column-reduction kernel (BIT-CRITICAL)
// ---------------------------------------------------------------------------
__global__ void colnorm_kernel(const float* __restrict__ Ad) {
    __shared__ float part[32][33];
    int tx = threadIdx.x;
    int ty = threadIdx.y;
    int w = blockIdx.x * 32 + tx;

    float s = 0.f;
    #pragma unroll
    for (int i = 0; i < Dd / 32; i++) {
        float v = Ad[(size_t)(ty + 32 * i) * Wd + w];
        s = __fadd_rn(s, __fmul_rn(v, v));
    }
    part[ty][tx] = s;
    __syncthreads();

    if (ty == 0) {
        float a[32];
        #pragma unroll
        for (int t = 0; t < 32; t++) a[t] = part[t][tx];
        #pragma unroll
        for (int off = 16; off > 0; off >>= 1)
            #pragma unroll
            for (int t2 = 0; t2 < 16; t2++)
                if (t2 < off)
                    a[t2] = __fadd_rn(a[t2], a[t2 + off]);
        g_nrm[w] = fmaxf(__fsqrt_rn(a[0]), 1e-8f);
    }
}

// ---------------------------------------------------------------------------
// 2) Normalize with IEEE fp32 division (BIT-CRITICAL) + transpose.
// ---------------------------------------------------------------------------
__global__ void scale_kernel(const float* __restrict__ Ad) {
    size_t i = (size_t)blockIdx.x * blockDim.x + threadIdx.x;
    if (i >= (size_t)Dd * Wd) return;
    int d = (int)(i / Wd);
    int w = (int)(i % Wd);
    float v = __fdiv_rn(Ad[i], g_nrm[w]);
    g_Adn[i] = v;
    g_AdnT[(size_t)w * Dd + d] = v;
}

// ---------------------------------------------------------------------------
// 2b) xm = x - bd  (screen input; z0 GEMM then needs no bias fusion)
// ---------------------------------------------------------------------------
__global__ void xminus_kernel(const float* __restrict__ x,
                              const float* __restrict__ bd) {
    size_t i = (size_t)blockIdx.x * blockDim.x + threadIdx.x;
    if (i >= (size_t)Bsz * Dd) return;
    g_Xm[i] = __fsub_rn(x[i], bd[(int)(i % Dd)]);
}

// ---------------------------------------------------------------------------
// 3) tf32 tensor-core GEMM, cp.async double-buffered (screen accuracy).
//    C[M,N] = A[M,K] @ B[K,N].  Raw fp32 fed to mma.tf32 (HW truncates).
//    OUT 0: fp32 C.   OUT 1: fp16 C, symmetric (skip by>bx, mirror-write).
//    BM=BN=128, BK=32, 256 thr, 8 warps (2m x 4n), warp tile 64x32.
//    Dynamic smem: 2 stages x (A 128x36 + B 32x136) floats = 70 KB.
// ---------------------------------------------------------------------------
__device__ __forceinline__ void mma_tf32(
    float& d0, float& d1, float& d2, float& d3,
    float a0, float a1, float a2, float a3,
    float b0, float b1)
{
    asm volatile(
        "mma.sync.aligned.m16n8k8.row.col.f32.tf32.tf32.f32 "
        "{%0,%1,%2,%3}, {%4,%5,%6,%7}, {%8,%9}, {%0,%1,%2,%3};\n"
        : "+f"(d0), "+f"(d1), "+f"(d2), "+f"(d3)
        : "r"(__float_as_uint(a0)), "r"(__float_as_uint(a1)),
          "r"(__float_as_uint(a2)), "r"(__float_as_uint(a3)),
          "r"(__float_as_uint(b0)), "r"(__float_as_uint(b1)));
}

#define GEMM_ASTR 36
#define GEMM_BSTR 136
#define GEMM_ASZ (128 * GEMM_ASTR)
#define GEMM_BSZ (32 * GEMM_BSTR)
#define GEMM_SMEM (2 * (GEMM_ASZ + GEMM_BSZ) * 4)

template<int OUT>
__global__ __launch_bounds__(256)
void gemm_tf32_pipe(const float* __restrict__ A,
                    const float* __restrict__ Bm,
                    void* __restrict__ Cv,
                    int M, int N, int Kd)
{
    extern __shared__ float smem[];
    float* As = smem;                      // [2][GEMM_ASZ]
    float* Bs = smem + 2 * GEMM_ASZ;       // [2][GEMM_BSZ]

    if (OUT == 1 && blockIdx.y > blockIdx.x) return;

    int tid  = threadIdx.x;
    int lane = tid & 31;
    int warp = tid >> 5;
    int wm = warp >> 2;
    int wn = warp & 3;

    int m0 = blockIdx.y * 128;
    int n0 = blockIdx.x * 128;

    float acc[4][4][4] = {};

    auto load_stage = [&](int s, int k0) {
        #pragma unroll
        for (int p = 0; p < 4; p++) {
            int id = tid + p * 256;
            int r = id >> 3;
            int c = (id & 7) * 4;
            uint32_t sa = (uint32_t)__cvta_generic_to_shared(
                &As[s * GEMM_ASZ + r * GEMM_ASTR + c]);
            const float* gp = A + (size_t)(m0 + r) * Kd + k0 + c;
            asm volatile("cp.async.cg.shared.global [%0], [%1], 16;\n"
                         :: "r"(sa), "l"(gp));
        }
        #pragma unroll
        for (int p = 0; p < 4; p++) {
            int id = tid + p * 256;
            int kr = id >> 5;
            int nc = (id & 31) * 4;
            uint32_t sb = (uint32_t)__cvta_generic_to_shared(
                &Bs[s * GEMM_BSZ + kr * GEMM_BSTR + nc]);
            const float* gp = Bm + (size_t)(k0 + kr) * N + n0 + nc;
            asm volatile("cp.async.cg.shared.global [%0], [%1], 16;\n"
                         :: "r"(sb), "l"(gp));
        }
        asm volatile("cp.async.commit_group;\n");
    };

    int T = Kd / 32;
    load_stage(0, 0);

    for (int i = 0; i < T; i++) {
        int cur = i & 1;
        if (i + 1 < T) {
            load_stage((i + 1) & 1, (i + 1) * 32);
            asm volatile("cp.async.wait_group 1;\n");
        } else {
            asm volatile("cp.async.wait_group 0;\n");
        }
        __syncthreads();

        const float* Ac = &As[cur * GEMM_ASZ];
        const float* Bc = &Bs[cur * GEMM_BSZ];
        #pragma unroll
        for (int ks = 0; ks < 4; ks++) {
            int kc = ks * 8;
            float af[4][4];
            #pragma unroll
            for (int mi = 0; mi < 4; mi++) {
                int r0 = wm * 64 + mi * 16 + (lane >> 2);
                int c0 = kc + (lane & 3);
                af[mi][0] = Ac[r0 * GEMM_ASTR + c0];
                af[mi][1] = Ac[(r0 + 8) * GEMM_ASTR + c0];
                af[mi][2] = Ac[r0 * GEMM_ASTR + c0 + 4];
                af[mi][3] = Ac[(r0 + 8) * GEMM_ASTR + c0 + 4];
            }
            float bf[4][2];
            #pragma unroll
            for (int ni = 0; ni < 4; ni++) {
                int nb = wn * 32 + ni * 8 + (lane >> 2);
                int kb = kc + (lane & 3);
                bf[ni][0] = Bc[kb * GEMM_BSTR + nb];
                bf[ni][1] = Bc[(kb + 4) * GEMM_BSTR + nb];
            }
            #pragma unroll
            for (int mi = 0; mi < 4; mi++)
                #pragma unroll
                for (int ni = 0; ni < 4; ni++)
                    mma_tf32(acc[mi][ni][0], acc[mi][ni][1],
                             acc[mi][ni][2], acc[mi][ni][3],
                             af[mi][0], af[mi][1], af[mi][2], af[mi][3],
                             bf[ni][0], bf[ni][1]);
        }
        __syncthreads();
    }

    if (OUT == 0) {
        float* C = (float*)Cv;
        #pragma unroll
        for (int mi = 0; mi < 4; mi++) {
            int rb = m0 + wm * 64 + mi * 16 + (lane >> 2);
            #pragma unroll
            for (int ni = 0; ni < 4; ni++) {
                int cb = n0 + wn * 32 + ni * 8 + 2 * (lane & 3);
                C[(size_t)rb * N + cb]           = acc[mi][ni][0];
                C[(size_t)rb * N + cb + 1]       = acc[mi][ni][1];
                C[(size_t)(rb + 8) * N + cb]     = acc[mi][ni][2];
                C[(size_t)(rb + 8) * N + cb + 1] = acc[mi][ni][3];
            }
        }
    } else {
        __half* C = (__half*)Cv;
        #pragma unroll
        for (int mi = 0; mi < 4; mi++) {
            int rb = m0 + wm * 64 + mi * 16 + (lane >> 2);
            #pragma unroll
            for (int ni = 0; ni < 4; ni++) {
                int cb = n0 + wn * 32 + ni * 8 + 2 * (lane & 3);
                __half h0 = __float2half(acc[mi][ni][0]);
                __half h1 = __float2half(acc[mi][ni][1]);
                __half h2 = __float2half(acc[mi][ni][2]);
                __half h3 = __float2half(acc[mi][ni][3]);
                C[(size_t)rb * N + cb]           = h0;
                C[(size_t)rb * N + cb + 1]       = h1;
                C[(size_t)(rb + 8) * N + cb]     = h2;
                C[(size_t)(rb + 8) * N + cb + 1] = h3;
                if (blockIdx.x != blockIdx.y) {
                    C[(size_t)cb * N + rb]           = h0;
                    C[(size_t)(cb + 1) * N + rb]     = h1;
                    C[(size_t)cb * N + rb + 8]       = h2;
                    C[(size_t)(cb + 1) * N + rb + 8] = h3;
                }
            }
        }
    }
}

// ---------------------------------------------------------------------------
// 4) Matching pursuit. BIT-CRITICAL ops unchanged (resid fsub/fmul, smem-
//    staged single ascending fp32 FMA chains, lowest-index strict max).
//    Screen: z fp32 in smem, G rows read as fp16 (half traffic, L2-resident).
// ---------------------------------------------------------------------------
__global__ __launch_bounds__(256)
void mp_kernel(const float* __restrict__ x, const float* __restrict__ bd,
               float* __restrict__ out)
{
    __shared__ __align__(16) float z[Wd];
    __shared__ __align__(16) float resid[Dd];
    __shared__ __align__(16) float cbuf[2 * CSTR];
    __shared__ int   selIdx[Kp];
    __shared__ float selVal[Kp];
    __shared__ int   sIdx2[Kp];
    __shared__ float sVal2[Kp];
    __shared__ int   candW[MAXCAND];
    __shared__ float candZ[MAXCAND];
    __shared__ int   candCount;
    __shared__ int   sMaxBits;

    int b = blockIdx.x;
    int t = threadIdx.x;

    // resid0 = x - bd (BIT-CRITICAL)
    for (int d = t; d < Dd; d += 256)
        resid[d] = __fsub_rn(x[(size_t)b * Dd + d], bd[d]);
    {
        const float* zg = g_Z + (size_t)b * Wd;
        #pragma unroll
        for (int i = 0; i < 8; i++) {
            int base = i * 1024 + t * 4;
            *(float4*)(&z[base]) = *(const float4*)(zg + base);
        }
    }
    __syncthreads();

    for (int k = 0; k < Kp; ++k) {
        // --- Phase A: max |z| via shared atomicMax on float bits ---
        if (t == 0) { sMaxBits = 0; candCount = 0; }
        __syncthreads();
        {
            float bv = 0.f;
            #pragma unroll
            for (int i = 0; i < 8; i++) {
                float4 v = *(const float4*)(&z[i * 1024 + t * 4]);
                bv = fmaxf(bv, fmaxf(fmaxf(fabsf(v.x), fabsf(v.y)),
                                     fmaxf(fabsf(v.z), fabsf(v.w))));
            }
            atomicMax(&sMaxBits, __float_as_int(bv));
        }
        __syncthreads();
        float M = __int_as_float(sMaxBits);

        // --- Phase B: collect candidates within TAU of max ---
        float thr = M - TAU;
        #pragma unroll
        for (int i = 0; i < 8; i++) {
            int base = i * 1024 + t * 4;
            float4 v = *(const float4*)(&z[base]);
            #pragma unroll
            for (int j = 0; j < 4; j++) {
                float a = fabsf(((const float*)&v)[j]);
                if (a >= thr) {
                    int pos = atomicAdd(&candCount, 1);
                    if (pos < MAXCAND) candW[pos] = base + j;
                }
            }
        }
        __syncthreads();
        int n = candCount < MAXCAND ? candCount : MAXCAND;

        if (t == 0) {
            for (int i = 1; i < n; i++) {
                int key = candW[i]; int j = i - 1;
                while (j >= 0 && candW[j] > key) { candW[j+1] = candW[j]; j--; }
                candW[j+1] = key;
            }
        }
        __syncthreads();

        // --- Phase C: stage rows + BIT-CRITICAL serial fp32 FMA chains ---
        for (int base = 0; base < n; base += 2) {
            int cnt = n - base; if (cnt > 2) cnt = 2;
            for (int r = 0; r < cnt; r++) {
                const float* arow = g_AdnT + (size_t)candW[base + r] * Dd;
                if (t < 192)
                    *(float4*)(&cbuf[r * CSTR + t * 4]) =
                        *(const float4*)(arow + t * 4);
            }
            __syncthreads();
            if (t < cnt) {
                const float* crow = &cbuf[t * CSTR];
                float acc = 0.f;
                #pragma unroll 16
                for (int d = 0; d < Dd; d++)
                    acc = __fmaf_rn(resid[d], crow[d], acc);
                candZ[base + t] = acc;
            }
            __syncthreads();
        }

        // --- Phase D: lowest-index strict max of |exact z| ---
        if (t == 0) {
            int best = 0;
            for (int i = 1; i < n; i++)
                if (fabsf(candZ[i]) > fabsf(candZ[best])) best = i;
            selIdx[k] = candW[best];
            selVal[k] = candZ[best];
        }
        __syncthreads();
        int   idx = selIdx[k];
        float val = selVal[k];

        // --- Phase E: updates ---
        if (k < Kp - 1) {
            // BIT-CRITICAL residual update
            const float* arow = g_AdnT + (size_t)idx * Dd;
            for (int d = t; d < Dd; d += 256)
                resid[d] = __fsub_rn(resid[d], __fmul_rn(val, arow[d]));

            // screen z update from fp16 G row (int4 = 8 halves per load)
            const __half* grow = g_Gh + (size_t)idx * Wd;
            #pragma unroll
            for (int i = 0; i < 4; i++) {
                int base = i * 2048 + t * 8;
                int4 raw = *(const int4*)(grow + base);
                const __half2* h = (const __half2*)&raw;
                float2 f0 = __half22float2(h[0]);
                float2 f1 = __half22float2(h[1]);
                float2 f2 = __half22float2(h[2]);
                float2 f3 = __half22float2(h[3]);
                float4 za = *(const float4*)(&z[base]);
                float4 zb = *(const float4*)(&z[base + 4]);
                za.x = fmaf(-val, f0.x, za.x);
                za.y = fmaf(-val, f0.y, za.y);
                za.z = fmaf(-val, f1.x, za.z);
                za.w = fmaf(-val, f1.y, za.w);
                zb.x = fmaf(-val, f2.x, zb.x);
                zb.y = fmaf(-val, f2.y, zb.y);
                zb.z = fmaf(-val, f3.x, zb.z);
                zb.w = fmaf(-val, f3.y, zb.w);
                *(float4*)(&z[base])     = za;
                *(float4*)(&z[base + 4]) = zb;
            }
            __syncthreads();
            if (t <= k) z[selIdx[t]] = 0.f;
        }
        __syncthreads();
    }

    // --- reconstruction: ascending-idx FMA chain + bd ---
    if (t == 0) {
        for (int i = 0; i < Kp; i++) { sIdx2[i] = selIdx[i]; sVal2[i] = selVal[i]; }
        for (int i = 1; i < Kp; i++) {
            int ki = sIdx2[i]; float kv = sVal2[i]; int j = i - 1;
            while (j >= 0 && sIdx2[j] > ki) {
                sIdx2[j+1] = sIdx2[j]; sVal2[j+1] = sVal2[j]; j--;
            }
            sIdx2[j+1] = ki; sVal2[j+1] = kv;
        }
    }
    __syncthreads();

    #pragma unroll
    for (int j = 0; j < 3; j++) {
        int d = t + j * 256;
        float acc = 0.f;
        #pragma unroll 1
        for (int i = 0; i < Kp; i++)
            acc = __fmaf_rn(sVal2[i], g_AdnT[(size_t)sIdx2[i] * Dd + d], acc);
        out[(size_t)b * Dd + d] = __fadd_rn(acc, bd[d]);
    }
}

// ---------------------------------------------------------------------------
// Launch
// ---------------------------------------------------------------------------
extern "C" void kernel_launch(void* const* d_in, const int* in_sizes, int n_in,
                              void* d_out, int out_size)
{
    const float* x  = (const float*)d_in[0];   // [B, D]
    const float* Ad = (const float*)d_in[1];   // [D, W]
    const float* bd = (const float*)d_in[2];   // [1, D]
    float* out = (float*)d_out;                // [B, D]

    float *p_Adn, *p_AdnT, *p_Z, *p_Xm;
    __half* p_Gh;
    cudaGetSymbolAddress((void**)&p_Adn,  g_Adn);
    cudaGetSymbolAddress((void**)&p_AdnT, g_AdnT);
    cudaGetSymbolAddress((void**)&p_Gh,   g_Gh);
    cudaGetSymbolAddress((void**)&p_Z,    g_Z);
    cudaGetSymbolAddress((void**)&p_Xm,   g_Xm);

    cudaFuncSetAttribute(gemm_tf32_pipe<0>,
                         cudaFuncAttributeMaxDynamicSharedMemorySize, GEMM_SMEM);
    cudaFuncSetAttribute(gemm_tf32_pipe<1>,
                         cudaFuncAttributeMaxDynamicSharedMemorySize, GEMM_SMEM);

    // 1) column norms (XLA:GPU column-reduce order — BIT-CRITICAL)
    colnorm_kernel<<<Wd / 32, dim3(32, 32)>>>(Ad);

    // 2) normalize + transpose (BIT-CRITICAL)
    {
        size_t total = (size_t)Dd * Wd;
        scale_kernel<<<(int)((total + 255) / 256), 256>>>(Ad);
    }

    // 2b) xm = x - bd (screen input)
    {
        size_t total = (size_t)Bsz * Dd;
        xminus_kernel<<<(int)((total + 255) / 256), 256>>>(x, bd);
    }

    // 3) G = AdnT @ Adn  (symmetric, fp16 out, cp.async pipelined)
    gemm_tf32_pipe<1><<<dim3(Wd / 128, Wd / 128), 256, GEMM_SMEM>>>(
        p_AdnT, p_Adn, p_Gh, Wd, Wd, Dd);

    // 4) z0 = xm @ Adn  (fp32 out, cp.async pipelined)
    gemm_tf32_pipe<0><<<dim3(Wd / 128, Bsz / 128), 256, GEMM_SMEM>>>(
        p_Xm, p_Adn, p_Z, Bsz, Wd, Dd);

    // 5) matching pursuit with reference-exact selection + reconstruction
    mp_kernel<<<Bsz, 256>>>(x, bd, out);
}

// round 17
// speedup vs baseline: 2.7412x; 1.0872x over previous
#include <cuda_runtime.h>
#include <cuda_fp16.h>
#include <cstdint>

// Problem constants
#define Bsz 8192
#define Dd  768
#define Wd  8192
#define Kp  32
#define TAU 5e-3f
#define MAXCAND 24
#define CSTR 772   // staged candidate row stride in floats (768 + 4, 16B-aligned)

// Device scratch (allocation-free rule: __device__ globals)
__device__ float  g_Adn [(size_t)Dd * Wd];   // [D, W] normalized dictionary (bit-exact)
__device__ float  g_AdnT[(size_t)Wd * Dd];   // [W, D] transpose (same bits)
__device__ float  g_nrm [Wd];                // clipped column norms (ref order)
__device__ __half g_Gh  [(size_t)Wd * Wd];   // Gram matrix (fp16, screen accuracy)
__device__ float  g_Z   [(size_t)Bsz * Wd];  // initial projections (screen accuracy)
__device__ float  g_Xm  [(size_t)Bsz * Dd];  // x - bd (screen input to z0 GEMM)

// ---------------------------------------------------------------------------
// 1) Column norms emulating the XLA:GPU column-reduction kernel (BIT-CRITICAL)
// ---------------------------------------------------------------------------
__global__ void colnorm_kernel(const float* __restrict__ Ad) {
    __shared__ float part[32][33];
    int tx = threadIdx.x;
    int ty = threadIdx.y;
    int w = blockIdx.x * 32 + tx;

    float s = 0.f;
    #pragma unroll
    for (int i = 0; i < Dd / 32; i++) {
        float v = Ad[(size_t)(ty + 32 * i) * Wd + w];
        s = __fadd_rn(s, __fmul_rn(v, v));
    }
    part[ty][tx] = s;
    __syncthreads();

    if (ty == 0) {
        float a[32];
        #pragma unroll
        for (int t = 0; t < 32; t++) a[t] = part[t][tx];
        #pragma unroll
        for (int off = 16; off > 0; off >>= 1)
            #pragma unroll
            for (int t2 = 0; t2 < 16; t2++)
                if (t2 < off)
                    a[t2] = __fadd_rn(a[t2], a[t2 + off]);
        g_nrm[w] = fmaxf(__fsqrt_rn(a[0]), 1e-8f);
    }
}

// ---------------------------------------------------------------------------
// 2) Normalize with IEEE fp32 division (BIT-CRITICAL) + transpose.
// ---------------------------------------------------------------------------
__global__ void scale_kernel(const float* __restrict__ Ad) {
    size_t i = (size_t)blockIdx.x * blockDim.x + threadIdx.x;
    if (i >= (size_t)Dd * Wd) return;
    int d = (int)(i / Wd);
    int w = (int)(i % Wd);
    float v = __fdiv_rn(Ad[i], g_nrm[w]);
    g_Adn[i] = v;
    g_AdnT[(size_t)w * Dd + d] = v;
}

// ---------------------------------------------------------------------------
// 2b) xm = x - bd (screen input)
// ---------------------------------------------------------------------------
__global__ void xminus_kernel(const float* __restrict__ x,
                              const float* __restrict__ bd) {
    size_t i = (size_t)blockIdx.x * blockDim.x + threadIdx.x;
    if (i >= (size_t)Bsz * Dd) return;
    g_Xm[i] = __fsub_rn(x[i], bd[(int)(i % Dd)]);
}

// ---------------------------------------------------------------------------
// 3) tf32 tensor-core GEMM, cp.async double-buffered (screen accuracy).
//    OUT 0: fp32 C.  OUT 1: fp16 C, symmetric (skip by>bx, mirror-write).
// ---------------------------------------------------------------------------
__device__ __forceinline__ void mma_tf32(
    float& d0, float& d1, float& d2, float& d3,
    float a0, float a1, float a2, float a3,
    float b0, float b1)
{
    asm volatile(
        "mma.sync.aligned.m16n8k8.row.col.f32.tf32.tf32.f32 "
        "{%0,%1,%2,%3}, {%4,%5,%6,%7}, {%8,%9}, {%0,%1,%2,%3};\n"
        : "+f"(d0), "+f"(d1), "+f"(d2), "+f"(d3)
        : "r"(__float_as_uint(a0)), "r"(__float_as_uint(a1)),
          "r"(__float_as_uint(a2)), "r"(__float_as_uint(a3)),
          "r"(__float_as_uint(b0)), "r"(__float_as_uint(b1)));
}

#define GEMM_ASTR 36
#define GEMM_BSTR 136
#define GEMM_ASZ (128 * GEMM_ASTR)
#define GEMM_BSZ (32 * GEMM_BSTR)
#define GEMM_SMEM (2 * (GEMM_ASZ + GEMM_BSZ) * 4)

template<int OUT>
__global__ __launch_bounds__(256, 2)
void gemm_tf32_pipe(const float* __restrict__ A,
                    const float* __restrict__ Bm,
                    void* __restrict__ Cv,
                    int M, int N, int Kd)
{
    extern __shared__ float smem[];
    float* As = smem;
    float* Bs = smem + 2 * GEMM_ASZ;

    if (OUT == 1 && blockIdx.y > blockIdx.x) return;

    int tid  = threadIdx.x;
    int lane = tid & 31;
    int warp = tid >> 5;
    int wm = warp >> 2;
    int wn = warp & 3;

    int m0 = blockIdx.y * 128;
    int n0 = blockIdx.x * 128;

    float acc[4][4][4] = {};

    auto load_stage = [&](int s, int k0) {
        #pragma unroll
        for (int p = 0; p < 4; p++) {
            int id = tid + p * 256;
            int r = id >> 3;
            int c = (id & 7) * 4;
            uint32_t sa = (uint32_t)__cvta_generic_to_shared(
                &As[s * GEMM_ASZ + r * GEMM_ASTR + c]);
            const float* gp = A + (size_t)(m0 + r) * Kd + k0 + c;
            asm volatile("cp.async.cg.shared.global [%0], [%1], 16;\n"
                         :: "r"(sa), "l"(gp));
        }
        #pragma unroll
        for (int p = 0; p < 4; p++) {
            int id = tid + p * 256;
            int kr = id >> 5;
            int nc = (id & 31) * 4;
            uint32_t sb = (uint32_t)__cvta_generic_to_shared(
                &Bs[s * GEMM_BSZ + kr * GEMM_BSTR + nc]);
            const float* gp = Bm + (size_t)(k0 + kr) * N + n0 + nc;
            asm volatile("cp.async.cg.shared.global [%0], [%1], 16;\n"
                         :: "r"(sb), "l"(gp));
        }
        asm volatile("cp.async.commit_group;\n");
    };

    int T = Kd / 32;
    load_stage(0, 0);

    for (int i = 0; i < T; i++) {
        int cur = i & 1;
        if (i + 1 < T) {
            load_stage((i + 1) & 1, (i + 1) * 32);
            asm volatile("cp.async.wait_group 1;\n");
        } else {
            asm volatile("cp.async.wait_group 0;\n");
        }
        __syncthreads();

        const float* Ac = &As[cur * GEMM_ASZ];
        const float* Bc = &Bs[cur * GEMM_BSZ];
        #pragma unroll
        for (int ks = 0; ks < 4; ks++) {
            int kc = ks * 8;
            float af[4][4];
            #pragma unroll
            for (int mi = 0; mi < 4; mi++) {
                int r0 = wm * 64 + mi * 16 + (lane >> 2);
                int c0 = kc + (lane & 3);
                af[mi][0] = Ac[r0 * GEMM_ASTR + c0];
                af[mi][1] = Ac[(r0 + 8) * GEMM_ASTR + c0];
                af[mi][2] = Ac[r0 * GEMM_ASTR + c0 + 4];
                af[mi][3] = Ac[(r0 + 8) * GEMM_ASTR + c0 + 4];
            }
            float bf[4][2];
            #pragma unroll
            for (int ni = 0; ni < 4; ni++) {
                int nb = wn * 32 + ni * 8 + (lane >> 2);
                int kb = kc + (lane & 3);
                bf[ni][0] = Bc[kb * GEMM_BSTR + nb];
                bf[ni][1] = Bc[(kb + 4) * GEMM_BSTR + nb];
            }
            #pragma unroll
            for (int mi = 0; mi < 4; mi++)
                #pragma unroll
                for (int ni = 0; ni < 4; ni++)
                    mma_tf32(acc[mi][ni][0], acc[mi][ni][1],
                             acc[mi][ni][2], acc[mi][ni][3],
                             af[mi][0], af[mi][1], af[mi][2], af[mi][3],
                             bf[ni][0], bf[ni][1]);
        }
        __syncthreads();
    }

    if (OUT == 0) {
        float* C = (float*)Cv;
        #pragma unroll
        for (int mi = 0; mi < 4; mi++) {
            int rb = m0 + wm * 64 + mi * 16 + (lane >> 2);
            #pragma unroll
            for (int ni = 0; ni < 4; ni++) {
                int cb = n0 + wn * 32 + ni * 8 + 2 * (lane & 3);
                C[(size_t)rb * N + cb]           = acc[mi][ni][0];
                C[(size_t)rb * N + cb + 1]       = acc[mi][ni][1];
                C[(size_t)(rb + 8) * N + cb]     = acc[mi][ni][2];
                C[(size_t)(rb + 8) * N + cb + 1] = acc[mi][ni][3];
            }
        }
    } else {
        __half* C = (__half*)Cv;
        #pragma unroll
        for (int mi = 0; mi < 4; mi++) {
            int rb = m0 + wm * 64 + mi * 16 + (lane >> 2);
            #pragma unroll
            for (int ni = 0; ni < 4; ni++) {
                int cb = n0 + wn * 32 + ni * 8 + 2 * (lane & 3);
                __half h0 = __float2half(acc[mi][ni][0]);
                __half h1 = __float2half(acc[mi][ni][1]);
                __half h2 = __float2half(acc[mi][ni][2]);
                __half h3 = __float2half(acc[mi][ni][3]);
                C[(size_t)rb * N + cb]           = h0;
                C[(size_t)rb * N + cb + 1]       = h1;
                C[(size_t)(rb + 8) * N + cb]     = h2;
                C[(size_t)(rb + 8) * N + cb + 1] = h3;
                if (blockIdx.x != blockIdx.y) {
                    C[(size_t)cb * N + rb]           = h0;
                    C[(size_t)(cb + 1) * N + rb]     = h1;
                    C[(size_t)cb * N + rb + 8]       = h2;
                    C[(size_t)(cb + 1) * N + rb + 8] = h3;
                }
            }
        }
    }
}

// ---------------------------------------------------------------------------
// 4) Matching pursuit v3. BIT-CRITICAL ops byte-identical: resid fsub/fmul
//    elementwise; candidate dots = single ascending fp32 FMA chain (float4
//    smem loads, same operand order); lowest-index strict max.
//    Screen opts: mask-bitset fused into z update (+local max), G-row
//    register prefetch during the chain, resid update from staged cbuf.
// ---------------------------------------------------------------------------
__global__ __launch_bounds__(256)
void mp_kernel(const float* __restrict__ x, const float* __restrict__ bd,
               float* __restrict__ out)
{
    __shared__ __align__(16) float z[Wd];              // 32 KB screen
    __shared__ __align__(16) float resid[Dd];
    __shared__ __align__(16) float cbuf[2 * CSTR];
    __shared__ unsigned selMask[Wd / 32];              // 1 KB bitset
    __shared__ int   selIdx[Kp];
    __shared__ float selVal[Kp];
    __shared__ int   sIdx2[Kp];
    __shared__ float sVal2[Kp];
    __shared__ int   candW[MAXCAND];
    __shared__ float candZ[MAXCAND];
    __shared__ int   candCount;
    __shared__ int   sMaxBits;
    __shared__ int   sBest;

    int b = blockIdx.x;
    int t = threadIdx.x;

    // resid0 = x - bd (BIT-CRITICAL)
    for (int d = t; d < Dd; d += 256)
        resid[d] = __fsub_rn(x[(size_t)b * Dd + d], bd[d]);
    if (t < Wd / 32) selMask[t] = 0u;
    if (t == 0) { sMaxBits = 0; candCount = 0; }
    __syncthreads();

    // load z + initial max
    {
        const float* zg = g_Z + (size_t)b * Wd;
        float lm = 0.f;
        #pragma unroll
        for (int i = 0; i < 8; i++) {
            int base = i * 1024 + t * 4;
            float4 v = *(const float4*)(zg + base);
            *(float4*)(&z[base]) = v;
            lm = fmaxf(lm, fmaxf(fmaxf(fabsf(v.x), fabsf(v.y)),
                                 fmaxf(fabsf(v.z), fabsf(v.w))));
        }
        atomicMax(&sMaxBits, __float_as_int(lm));
    }
    __syncthreads();

    for (int k = 0; k < Kp; ++k) {
        float M = __int_as_float(sMaxBits);
        float thr = M - TAU;

        // --- collect candidates (selected entries are exact 0 in z) ---
        #pragma unroll
        for (int i = 0; i < 8; i++) {
            int base = i * 1024 + t * 4;
            float4 v = *(const float4*)(&z[base]);
            #pragma unroll
            for (int j = 0; j < 4; j++) {
                float a = fabsf(((const float*)&v)[j]);
                if (a >= thr) {
                    int pos = atomicAdd(&candCount, 1);
                    if (pos < MAXCAND) candW[pos] = base + j;
                }
            }
        }
        __syncthreads();
        int n = candCount < MAXCAND ? candCount : MAXCAND;
        if (n > 1) {
            if (t == 0) {
                for (int i = 1; i < n; i++) {
                    int key = candW[i]; int j = i - 1;
                    while (j >= 0 && candW[j] > key) { candW[j+1] = candW[j]; j--; }
                    candW[j+1] = key;
                }
            }
            __syncthreads();
        }

        // --- stage candidate rows (batches of 2) + prefetch G row (n==1) ---
        int  pidx = candW[0];
        int4 pre[4];
        bool pf = (n == 1) && (k < Kp - 1);
        int lastBase = ((n - 1) / 2) * 2;

        for (int base2 = 0; base2 < n; base2 += 2) {
            int cnt = n - base2; if (cnt > 2) cnt = 2;
            for (int r = 0; r < cnt; r++) {
                const float* arow = g_AdnT + (size_t)candW[base2 + r] * Dd;
                if (t < 192)
                    *(float4*)(&cbuf[r * CSTR + t * 4]) =
                        *(const float4*)(arow + t * 4);
            }
            if (pf && base2 == 0) {
                const __half* grow = g_Gh + (size_t)pidx * Wd;
                #pragma unroll
                for (int i = 0; i < 4; i++)
                    pre[i] = *(const int4*)(grow + i * 2048 + t * 8);
            }
            __syncthreads();
            // BIT-CRITICAL: single ascending fp32 FMA chain (float4 loads)
            if (t < cnt) {
                const float4* c4 = (const float4*)&cbuf[t * CSTR];
                const float4* r4 = (const float4*)resid;
                float acc = 0.f;
                #pragma unroll 8
                for (int q = 0; q < Dd / 4; q++) {
                    float4 rv = r4[q];
                    float4 cv = c4[q];
                    acc = __fmaf_rn(rv.x, cv.x, acc);
                    acc = __fmaf_rn(rv.y, cv.y, acc);
                    acc = __fmaf_rn(rv.z, cv.z, acc);
                    acc = __fmaf_rn(rv.w, cv.w, acc);
                }
                candZ[base2 + t] = acc;
            }
            __syncthreads();
        }

        // --- select: lowest-index strict max of |exact z|; set mask ---
        if (t == 0) {
            int best = 0;
            for (int i = 1; i < n; i++)
                if (fabsf(candZ[i]) > fabsf(candZ[best])) best = i;
            selIdx[k] = candW[best];
            selVal[k] = candZ[best];
            sBest = best;
            int idx0 = candW[best];
            selMask[idx0 >> 5] |= (1u << (idx0 & 31));
            candCount = 0;
            sMaxBits = 0;
        }
        __syncthreads();
        int   idx = selIdx[k];
        float val = selVal[k];

        if (k < Kp - 1) {
            // resid source: staged row if winner is in last batch, else restage
            const float* crow;
            if (sBest >= lastBase) {
                crow = &cbuf[(sBest - lastBase) * CSTR];
            } else {
                const float* arow = g_AdnT + (size_t)idx * Dd;
                if (t < 192)
                    *(float4*)(&cbuf[t * 4]) = *(const float4*)(arow + t * 4);
                __syncthreads();
                crow = cbuf;
            }
            // BIT-CRITICAL residual update: r = fsub(r, fmul(val, a))
            for (int d = t; d < Dd; d += 256)
                resid[d] = __fsub_rn(resid[d], __fmul_rn(val, crow[d]));

            // z update from fp16 G row, fused mask + local max
            const __half* grow = g_Gh + (size_t)idx * Wd;
            float lm = 0.f;
            #pragma unroll
            for (int i = 0; i < 4; i++) {
                int base = i * 2048 + t * 8;
                int4 raw = pf ? pre[i] : *(const int4*)(grow + base);
                const __half2* h = (const __half2*)&raw;
                float2 f0 = __half22float2(h[0]);
                float2 f1 = __half22float2(h[1]);
                float2 f2 = __half22float2(h[2]);
                float2 f3 = __half22float2(h[3]);
                unsigned mb = (selMask[base >> 5] >> (base & 31)) & 0xFFu;
                float4 za = *(const float4*)(&z[base]);
                float4 zb = *(const float4*)(&z[base + 4]);
                za.x = (mb & 0x01u) ? 0.f : fmaf(-val, f0.x, za.x);
                za.y = (mb & 0x02u) ? 0.f : fmaf(-val, f0.y, za.y);
                za.z = (mb & 0x04u) ? 0.f : fmaf(-val, f1.x, za.z);
                za.w = (mb & 0x08u) ? 0.f : fmaf(-val, f1.y, za.w);
                zb.x = (mb & 0x10u) ? 0.f : fmaf(-val, f2.x, zb.x);
                zb.y = (mb & 0x20u) ? 0.f : fmaf(-val, f2.y, zb.y);
                zb.z = (mb & 0x40u) ? 0.f : fmaf(-val, f3.x, zb.z);
                zb.w = (mb & 0x80u) ? 0.f : fmaf(-val, f3.y, zb.w);
                *(float4*)(&z[base])     = za;
                *(float4*)(&z[base + 4]) = zb;
                lm = fmaxf(lm, fmaxf(fmaxf(fabsf(za.x), fabsf(za.y)),
                                     fmaxf(fabsf(za.z), fabsf(za.w))));
                lm = fmaxf(lm, fmaxf(fmaxf(fabsf(zb.x), fabsf(zb.y)),
                                     fmaxf(fabsf(zb.z), fabsf(zb.w))));
            }
            atomicMax(&sMaxBits, __float_as_int(lm));
        }
        __syncthreads();
    }

    // --- reconstruction: ascending-idx FMA chain + bd ---
    if (t == 0) {
        for (int i = 0; i < Kp; i++) { sIdx2[i] = selIdx[i]; sVal2[i] = selVal[i]; }
        for (int i = 1; i < Kp; i++) {
            int ki = sIdx2[i]; float kv = sVal2[i]; int j = i - 1;
            while (j >= 0 && sIdx2[j] > ki) {
                sIdx2[j+1] = sIdx2[j]; sVal2[j+1] = sVal2[j]; j--;
            }
            sIdx2[j+1] = ki; sVal2[j+1] = kv;
        }
    }
    __syncthreads();

    #pragma unroll
    for (int j = 0; j < 3; j++) {
        int d = t + j * 256;
        float acc = 0.f;
        #pragma unroll 1
        for (int i = 0; i < Kp; i++)
            acc = __fmaf_rn(sVal2[i], g_AdnT[(size_t)sIdx2[i] * Dd + d], acc);
        out[(size_t)b * Dd + d] = __fadd_rn(acc, bd[d]);
    }
}

// ---------------------------------------------------------------------------
// Launch
// ---------------------------------------------------------------------------
extern "C" void kernel_launch(void* const* d_in, const int* in_sizes, int n_in,
                              void* d_out, int out_size)
{
    const float* x  = (const float*)d_in[0];   // [B, D]
    const float* Ad = (const float*)d_in[1];   // [D, W]
    const float* bd = (const float*)d_in[2];   // [1, D]
    float* out = (float*)d_out;                // [B, D]

    float *p_Adn, *p_AdnT, *p_Z, *p_Xm;
    __half* p_Gh;
    cudaGetSymbolAddress((void**)&p_Adn,  g_Adn);
    cudaGetSymbolAddress((void**)&p_AdnT, g_AdnT);
    cudaGetSymbolAddress((void**)&p_Gh,   g_Gh);
    cudaGetSymbolAddress((void**)&p_Z,    g_Z);
    cudaGetSymbolAddress((void**)&p_Xm,   g_Xm);

    cudaFuncSetAttribute(gemm_tf32_pipe<0>,
                         cudaFuncAttributeMaxDynamicSharedMemorySize, GEMM_SMEM);
    cudaFuncSetAttribute(gemm_tf32_pipe<1>,
                         cudaFuncAttributeMaxDynamicSharedMemorySize, GEMM_SMEM);

    // 1) column norms (XLA:GPU column-reduce order — BIT-CRITICAL)
    colnorm_kernel<<<Wd / 32, dim3(32, 32)>>>(Ad);

    // 2) normalize + transpose (BIT-CRITICAL)
    {
        size_t total = (size_t)Dd * Wd;
        scale_kernel<<<(int)((total + 255) / 256), 256>>>(Ad);
    }

    // 2b) xm = x - bd (screen input)
    {
        size_t total = (size_t)Bsz * Dd;
        xminus_kernel<<<(int)((total + 255) / 256), 256>>>(x, bd);
    }

    // 3) G = AdnT @ Adn  (symmetric, fp16 out, cp.async pipelined)
    gemm_tf32_pipe<1><<<dim3(Wd / 128, Wd / 128), 256, GEMM_SMEM>>>(
        p_AdnT, p_Adn, p_Gh, Wd, Wd, Dd);

    // 4) z0 = xm @ Adn  (fp32 out, cp.async pipelined)
    gemm_tf32_pipe<0><<<dim3(Wd / 128, Bsz / 128), 256, GEMM_SMEM>>>(
        p_Xm, p_Adn, p_Z, Bsz, Wd, Dd);

    // 5) matching pursuit with reference-exact selection + reconstruction
    mp_kernel<<<Bsz, 256>>>(x, bd, out);
}